// round 1
// baseline (speedup 1.0000x reference)
#include <cuda_runtime.h>
#include <math.h>

#define NB 48
#define NC 3
#define HH 256
#define WW 256

#define TW 128
#define TH 32
#define HT (TH + 10)       // 42 intermediate rows
#define WTIN (TW + 10)     // 138 input cols used
#define WPAD 144           // padded row stride (floats)
#define GX (WW / TW)       // 2
#define GY (HH / TH)       // 8
#define NIMG (NB * NC)     // 144
#define NBLK (GX * GY * NIMG) // 2304

#define C1S 1e-4f
#define C2S 9e-4f

// 1D Gaussian (k=11, sigma=1.5), normalized — compile-time constants so the
// conv taps become FFMA-imm (rt_SMSP=1 on sm_103a).
__device__ static constexpr float GK[11] = {
    0.00102840f, 0.00759880f, 0.03600060f, 0.10936270f, 0.21300441f,
    0.26601031f,
    0.21300441f, 0.10936270f, 0.03600060f, 0.00759880f, 0.00102840f
};

// Scratch (device globals: allocation-guard safe)
__device__ float g_wmap[NB * HH * WW];   // 12.6 MB
__device__ float g_part[NBLK];

// ---------------------------------------------------------------------------
// Kernel 1: per-batch weight map via scanline polygon crossings.
// Block = (row-group of 8 rows, n). 8 warps, 1 warp per row, no block barriers
// inside the row work (warp-local compaction via ballot/popc — deterministic).
// ---------------------------------------------------------------------------
__global__ void __launch_bounds__(256) wmap_kernel(const float* __restrict__ lm)
{
    __shared__ float lx[24], ly[24];
    __shared__ float bbx0[3], bbx1[3], bby0[3], bby1[3];
    __shared__ float validf[3];
    __shared__ float sxint[8][24];

    const int n = blockIdx.y;
    const int tid = threadIdx.x;
    const int warp = tid >> 5, lane = tid & 31;

    if (tid < 24) {
        lx[tid] = lm[(n * 68 + 36 + tid) * 2 + 0];
        ly[tid] = lm[(n * 68 + 36 + tid) * 2 + 1];
    }
    __syncthreads();
    if (tid < 3) {
        const int b = tid * 6;                  // 0, 6, 12
        const int np = (tid == 2) ? 12 : 6;
        float mnx = lx[b], mxx = lx[b], mny = ly[b], mxy = ly[b];
        for (int i = 1; i < np; i++) {
            float xv = lx[b + i], yv = ly[b + i];
            mnx = fminf(mnx, xv); mxx = fmaxf(mxx, xv);
            mny = fminf(mny, yv); mxy = fmaxf(mxy, yv);
        }
        float fx0 = floorf(mnx), fx1 = floorf(mxx);
        float fy0 = floorf(mny), fy1 = floorf(mxy);
        bbx0[tid] = fx0; bbx1[tid] = fx1; bby0[tid] = fy0; bby1[tid] = fy1;
        validf[tid] = (fx0 >= 0.f && fy0 >= 0.f &&
                       fx1 < (float)WW && fy1 < (float)HH) ? 1.f : 0.f;
    }
    __syncthreads();

    const int row = blockIdx.x * 8 + warp;
    const float Y = (float)row;

    bool strad = false;
    float xi = 0.f;
    int base = 0;
    if (lane < 24) {
        const int p = (lane < 6) ? 0 : (lane < 12) ? 1 : 2;
        base = p * 6;                           // 0, 6, 12
        const int np = (p == 2) ? 12 : 6;
        const float x1 = lx[lane], y1 = ly[lane];
        const int i2 = base + ((lane - base + 1) % np);
        const float x2 = lx[i2], y2 = ly[i2];
        strad = (y1 > Y) != (y2 > Y);
        xi = (x2 - x1) * (Y - y1) / (y2 - y1 + 1e-6f) + x1;
    }
    const unsigned m = __ballot_sync(0xffffffffu, strad);
    const unsigned m0 = m & 0x00003Fu;
    const unsigned m1 = m & 0x000FC0u;
    const unsigned m2 = m & 0xFFF000u;
    if (strad) {
        const unsigned mp = (lane < 6) ? m0 : (lane < 12) ? m1 : m2;
        const int slot = __popc(mp & ((1u << lane) - 1u));
        sxint[warp][base + slot] = xi;
    }
    __syncwarp();
    const int c0 = __popc(m0), c1 = __popc(m1), c2 = __popc(m2);

    float* __restrict__ bw = g_wmap + ((size_t)n * HH + row) * WW;
    for (int k = 0; k < 8; k++) {
        const int Xi = lane + 32 * k;
        const float X = (float)Xi;
        float w = 1.f;
        {   // eyes L (weight 3)
            float inb = (Y >= bby0[0] && Y < bby1[0] && X >= bbx0[0] && X < bbx1[0]) ? 1.f : 0.f;
            int cnt = 0;
            for (int s = 0; s < c0; s++) cnt += (X < sxint[warp][0 + s]) ? 1 : 0;
            w += 3.f * (validf[0] * inb * ((cnt & 1) ? 1.f : 0.f));
        }
        {   // eyes R (weight 3)
            float inb = (Y >= bby0[1] && Y < bby1[1] && X >= bbx0[1] && X < bbx1[1]) ? 1.f : 0.f;
            int cnt = 0;
            for (int s = 0; s < c1; s++) cnt += (X < sxint[warp][6 + s]) ? 1 : 0;
            w += 3.f * (validf[1] * inb * ((cnt & 1) ? 1.f : 0.f));
        }
        {   // mouth (weight 2)
            float inb = (Y >= bby0[2] && Y < bby1[2] && X >= bbx0[2] && X < bbx1[2]) ? 1.f : 0.f;
            int cnt = 0;
            for (int s = 0; s < c2; s++) cnt += (X < sxint[warp][12 + s]) ? 1 : 0;
            w += 2.f * (validf[2] * inb * ((cnt & 1) ? 1.f : 0.f));
        }
        bw[Xi] = w;
    }
}

// ---------------------------------------------------------------------------
// Kernel 2: fused SSIM convs + L1 + weighted L1, tile 128x32, 256 threads.
// Phase 0: global -> smem input tile (with zero halo), fused |p-t| terms.
// Phase 1: horizontal 11-tap conv of 5 moment fields, 4 cols/thread (LDS.128).
// Phase 2: vertical 11-tap conv, register-blocked 4 rows x 4 cols / thread,
//          then the SSIM pointwise formula; deterministic block reduce.
// ---------------------------------------------------------------------------
__global__ void __launch_bounds__(256, 1)
main_kernel(const float* __restrict__ pred, const float* __restrict__ targ)
{
    extern __shared__ float sm[];
    float* s_p = sm;                         // HT * WPAD
    float* s_t = sm + HT * WPAD;             // HT * WPAD
    float* s_h = sm + 2 * HT * WPAD;         // 5 * HT * TW
    float* s_r = s_h + 5 * HT * TW;          // 256

    const int tid = threadIdx.x;
    const int c0 = blockIdx.x * TW;
    const int r0 = blockIdx.y * TH;
    const int img = blockIdx.z;
    const int n = img / NC;

    const float* __restrict__ P = pred + (size_t)img * (HH * WW);
    const float* __restrict__ T = targ + (size_t)img * (HH * WW);
    const float* __restrict__ WM = g_wmap + (size_t)n * (HH * WW);

    float acc = 0.f;   // accumulates 10*ad + 5*w*ad + 5*(1-ssim)

    // ---- Phase 0: load tile with zero halo, fuse L1 terms ----
    for (int idx = tid; idx < HT * WPAD; idx += 256) {
        const int i = idx / WPAD;
        const int j = idx - i * WPAD;
        const int gr = r0 - 5 + i;
        const int gc = c0 - 5 + j;
        float pv = 0.f, tv = 0.f;
        if (j < WTIN && (unsigned)gr < HH && (unsigned)gc < WW) {
            pv = P[gr * WW + gc];
            tv = T[gr * WW + gc];
        }
        s_p[idx] = pv;
        s_t[idx] = tv;
        if (i >= 5 && i < 5 + TH && j >= 5 && j < 5 + TW) {
            const float ad = fabsf(pv - tv);
            const float w = WM[gr * WW + gc];
            acc += (10.f + 5.f * w) * ad;
        }
    }
    __syncthreads();

    // ---- Phase 1: horizontal conv of 5 fields ----
    for (int t2 = tid; t2 < HT * (TW / 4); t2 += 256) {
        const int i = t2 >> 5;      // row 0..41
        const int q = t2 & 31;      // quad-col 0..31
        const float4* rp = (const float4*)(s_p + i * WPAD + 4 * q);
        const float4* rt = (const float4*)(s_t + i * WPAD + 4 * q);
        float p[16], t[16];
        float4 v;
        v = rp[0]; p[0]=v.x; p[1]=v.y; p[2]=v.z; p[3]=v.w;
        v = rp[1]; p[4]=v.x; p[5]=v.y; p[6]=v.z; p[7]=v.w;
        v = rp[2]; p[8]=v.x; p[9]=v.y; p[10]=v.z; p[11]=v.w;
        v = rp[3]; p[12]=v.x; p[13]=v.y; p[14]=v.z; p[15]=v.w;
        v = rt[0]; t[0]=v.x; t[1]=v.y; t[2]=v.z; t[3]=v.w;
        v = rt[1]; t[4]=v.x; t[5]=v.y; t[6]=v.z; t[7]=v.w;
        v = rt[2]; t[8]=v.x; t[9]=v.y; t[10]=v.z; t[11]=v.w;
        v = rt[3]; t[12]=v.x; t[13]=v.y; t[14]=v.z; t[15]=v.w;

        float pp[14], tt[14], pt[14];
        #pragma unroll
        for (int u = 0; u < 14; u++) {
            pp[u] = p[u] * p[u];
            tt[u] = t[u] * t[u];
            pt[u] = p[u] * t[u];
        }
        float hx[4], hy[4], hxx[4], hyy[4], hxy[4];
        #pragma unroll
        for (int k = 0; k < 4; k++) {
            float a = 0.f, b = 0.f, c = 0.f, d = 0.f, e = 0.f;
            #pragma unroll
            for (int j = 0; j < 11; j++) {
                const float g = GK[j];
                a += g * p[k + j];
                b += g * t[k + j];
                c += g * pp[k + j];
                d += g * tt[k + j];
                e += g * pt[k + j];
            }
            hx[k] = a; hy[k] = b; hxx[k] = c; hyy[k] = d; hxy[k] = e;
        }
        const int off = i * TW + 4 * q;
        *(float4*)(s_h + 0 * HT * TW + off) = make_float4(hx[0], hx[1], hx[2], hx[3]);
        *(float4*)(s_h + 1 * HT * TW + off) = make_float4(hy[0], hy[1], hy[2], hy[3]);
        *(float4*)(s_h + 2 * HT * TW + off) = make_float4(hxx[0], hxx[1], hxx[2], hxx[3]);
        *(float4*)(s_h + 3 * HT * TW + off) = make_float4(hyy[0], hyy[1], hyy[2], hyy[3]);
        *(float4*)(s_h + 4 * HT * TW + off) = make_float4(hxy[0], hxy[1], hxy[2], hxy[3]);
    }
    __syncthreads();

    // ---- Phase 2: vertical conv (4 rows x 4 cols per thread) + SSIM ----
    {
        const int rg = tid >> 5;    // row group 0..7 (4 rows each)
        const int q = tid & 31;     // quad-col
        float ax[16], ay[16], axx[16], ayy[16], axy[16];
        #pragma unroll
        for (int m2 = 0; m2 < 16; m2++) {
            ax[m2] = 0.f; ay[m2] = 0.f; axx[m2] = 0.f; ayy[m2] = 0.f; axy[m2] = 0.f;
        }
        #pragma unroll
        for (int rr = 0; rr < 14; rr++) {
            const int row = rg * 4 + rr;
            const int off = row * TW + 4 * q;
            const float4 vx  = *(const float4*)(s_h + 0 * HT * TW + off);
            const float4 vy  = *(const float4*)(s_h + 1 * HT * TW + off);
            const float4 vxx = *(const float4*)(s_h + 2 * HT * TW + off);
            const float4 vyy = *(const float4*)(s_h + 3 * HT * TW + off);
            const float4 vxy = *(const float4*)(s_h + 4 * HT * TW + off);
            #pragma unroll
            for (int k = 0; k < 4; k++) {
                const int j = rr - k;
                if (j >= 0 && j < 11) {
                    const float g = GK[j];
                    ax[4*k+0]  += g * vx.x;  ax[4*k+1]  += g * vx.y;  ax[4*k+2]  += g * vx.z;  ax[4*k+3]  += g * vx.w;
                    ay[4*k+0]  += g * vy.x;  ay[4*k+1]  += g * vy.y;  ay[4*k+2]  += g * vy.z;  ay[4*k+3]  += g * vy.w;
                    axx[4*k+0] += g * vxx.x; axx[4*k+1] += g * vxx.y; axx[4*k+2] += g * vxx.z; axx[4*k+3] += g * vxx.w;
                    ayy[4*k+0] += g * vyy.x; ayy[4*k+1] += g * vyy.y; ayy[4*k+2] += g * vyy.z; ayy[4*k+3] += g * vyy.w;
                    axy[4*k+0] += g * vxy.x; axy[4*k+1] += g * vxy.y; axy[4*k+2] += g * vxy.z; axy[4*k+3] += g * vxy.w;
                }
            }
        }
        float sds = 0.f;
        #pragma unroll
        for (int m2 = 0; m2 < 16; m2++) {
            const float mx = ax[m2], my = ay[m2];
            const float sx = axx[m2] - mx * mx;
            const float sy = ayy[m2] - my * my;
            const float sxy = axy[m2] - mx * my;
            const float num = (2.f * mx * my + C1S) * (2.f * sxy + C2S);
            const float den = (mx * mx + my * my + C1S) * (sx + sy + C2S) + 1e-8f;
            const float ssim = __fdividef(num, den);
            sds += (1.f - ssim);
        }
        acc += 5.f * sds;   // 10 * (1-ssim)/2
    }

    // ---- deterministic block reduction ----
    s_r[tid] = acc;
    __syncthreads();
    for (int s = 128; s > 0; s >>= 1) {
        if (tid < s) s_r[tid] += s_r[tid + s];
        __syncthreads();
    }
    if (tid == 0) {
        g_part[(blockIdx.z * GY + blockIdx.y) * GX + blockIdx.x] = s_r[0];
    }
}

// ---------------------------------------------------------------------------
// Kernel 3: deterministic final reduction in double precision.
// ---------------------------------------------------------------------------
__global__ void __launch_bounds__(256) reduce_kernel(float* __restrict__ out)
{
    __shared__ double sd[256];
    const int tid = threadIdx.x;
    double s = 0.0;
    for (int i = tid; i < NBLK; i += 256) s += (double)g_part[i];
    sd[tid] = s;
    __syncthreads();
    for (int st = 128; st > 0; st >>= 1) {
        if (tid < st) sd[tid] += sd[tid + st];
        __syncthreads();
    }
    if (tid == 0) {
        out[0] = (float)(sd[0] / ((double)NB * (double)NC * (double)HH * (double)WW));
    }
}

extern "C" void kernel_launch(void* const* d_in, const int* in_sizes, int n_in,
                              void* d_out, int out_size)
{
    const float* pred = (const float*)d_in[0];
    const float* targ = (const float*)d_in[1];
    const float* lm   = (const float*)d_in[2];
    float* out = (float*)d_out;
    (void)in_sizes; (void)n_in; (void)out_size;

    wmap_kernel<<<dim3(HH / 8, NB), 256>>>(lm);

    const size_t smem = (size_t)(2 * HT * WPAD + 5 * HT * TW + 256) * sizeof(float);
    cudaFuncSetAttribute(main_kernel,
                         cudaFuncAttributeMaxDynamicSharedMemorySize, (int)smem);
    main_kernel<<<dim3(GX, GY, NIMG), 256, smem>>>(pred, targ);

    reduce_kernel<<<1, 256>>>(out);
}